// round 13
// baseline (speedup 1.0000x reference)
#include <cuda_runtime.h>

// decoder_fm — R9: two-phase within one graph.
//  k1: cp.async.bulk.prefetch.L2 of every gathered 256B embedding row (user+item)
//      plus linear prefetch of both bias arrays. Deep TMA-path queue raises
//      outstanding-miss MLP past the L1-MSHR cap that binds plain LDG gathers.
//  k2: R7 compute body (known-good): 8 rows/warp, 4 lanes/row, packed f32x2
//      math; gathers now hit L2 instead of queued DRAM.

#define PACK2(d, lo, hi)   asm("mov.b64 %0, {%1, %2};" : "=l"(d) : "f"(lo), "f"(hi))
#define UNPACK2(lo, hi, s) asm("mov.b64 {%0, %1}, %2;" : "=f"(lo), "=f"(hi) : "l"(s))
#define FMA2(d, a, b)      asm("fma.rn.f32x2 %0, %1, %2, %3;" : "=l"(d) : "l"(a), "l"(b), "l"(d))
#define ADD2(d, a, b)      asm("add.rn.f32x2 %0, %1, %2;" : "=l"(d) : "l"(a), "l"(b))

__device__ __forceinline__ void prefetch_l2_256(const void* p) {
    asm volatile("cp.async.bulk.prefetch.L2.global [%0], %1;" :: "l"(p), "r"(256u));
}

__device__ __forceinline__ unsigned long long mk_policy_keep() {
    unsigned long long p;
    asm("createpolicy.fractional.L2::evict_last.b64 %0, 1.0;" : "=l"(p));
    return p;
}
__device__ __forceinline__ float4 ldg_keep4(const float4* p, unsigned long long pol) {
    float4 v;
    asm("ld.global.nc.L2::cache_hint.v4.f32 {%0,%1,%2,%3}, [%4], %5;"
        : "=f"(v.x), "=f"(v.y), "=f"(v.z), "=f"(v.w) : "l"(p), "l"(pol));
    return v;
}
__device__ __forceinline__ float ldg_keep1(const float* p, unsigned long long pol) {
    float v;
    asm("ld.global.nc.L2::cache_hint.f32 %0, [%1], %2;" : "=f"(v) : "l"(p), "l"(pol));
    return v;
}

// ---------------- k1: prefetch ----------------
__global__ __launch_bounds__(256) void fm_prefetch_kernel(
    const int* __restrict__ user, const int* __restrict__ item,
    const float* __restrict__ user_emb, const float* __restrict__ item_emb,
    const float* __restrict__ b_users, const float* __restrict__ b_items,
    int nrows)
{
    const int t = blockIdx.x * blockDim.x + threadIdx.x;
    if (t < nrows) {
        const int u  = __ldg(user + t);
        const int it = __ldg(item + t);
        prefetch_l2_256(user_emb + (long long)u  * 64);   // 256B row
        prefetch_l2_256(item_emb + (long long)it * 64);   // 256B row
        // bias arrays: 1M floats = 4MB = 16384 x 256B chunks; linear prefetch
        prefetch_l2_256(b_users + (long long)t * 64);
        prefetch_l2_256(b_items + (long long)t * 64);
    }
}

// ---------------- k2: compute (R7 body) ----------------
__global__ __launch_bounds__(256) void fm_kernel(
    const int* __restrict__ user, const int* __restrict__ item,
    const float* __restrict__ user_emb, const float* __restrict__ item_emb,
    const float* __restrict__ fc_w, const float* __restrict__ fc_b,
    const float* __restrict__ fm_V,
    const float* __restrict__ b_users, const float* __restrict__ b_items,
    float* __restrict__ out, int nrows)
{
    __shared__ float2 sws[128];      // (fc_w[j], s_j)
    __shared__ float2 sV[5][128];    // (V[j][2k2], V[j][2k2+1])

    const int tid = threadIdx.x;
    if (tid < 128) {
        float v[10];
        #pragma unroll
        for (int k = 0; k < 10; k++) v[k] = fm_V[tid * 10 + k];
        float s = 0.f;
        #pragma unroll
        for (int k = 0; k < 10; k++) s = fmaf(v[k], v[k], s);
        sws[tid] = make_float2(fc_w[tid], s);
        #pragma unroll
        for (int k2 = 0; k2 < 5; k2++)
            sV[k2][tid] = make_float2(v[2 * k2], v[2 * k2 + 1]);
    }
    __syncthreads();

    const int lane = tid & 31;
    const int sub  = lane & 3;     // element slice within a row
    const int rw   = lane >> 2;    // row within warp (0..7)
    const int warp = tid >> 5;     // 0..7
    const int row  = blockIdx.x * 64 + warp * 8 + rw;
    if (row >= nrows) return;

    const unsigned long long pol = mk_policy_keep();

    const int u  = user[row];
    const int it = item[row];
    const float4* up = reinterpret_cast<const float4*>(user_emb + (long long)u  * 64);
    const float4* ip = reinterpret_cast<const float4*>(item_emb + (long long)it * 64);

    float4 xu[4], xi[4];
    #pragma unroll
    for (int c = 0; c < 4; c++) xu[c] = ldg_keep4(up + c * 4 + sub, pol);
    #pragma unroll
    for (int c = 0; c < 4; c++) xi[c] = ldg_keep4(ip + c * 4 + sub, pol);
    const float bu = ldg_keep1(b_users + u, pol);
    const float bi = ldg_keep1(b_items + it, pol);

    unsigned long long acc_ls = 0ull;   // (lin, x2s)
    unsigned long long acc2[5];         // xv pairs
    #pragma unroll
    for (int k2 = 0; k2 < 5; k2++) acc2[k2] = 0ull;

    #pragma unroll
    for (int h = 0; h < 2; h++) {
        #pragma unroll
        for (int c = 0; c < 4; c++) {
            const float4 xq = h ? xi[c] : xu[c];
            const int j0 = h * 64 + (c * 4 + sub) * 4;
            const float xs[4] = {xq.x, xq.y, xq.z, xq.w};

            const ulonglong2 wsA = *reinterpret_cast<const ulonglong2*>(&sws[j0]);
            const ulonglong2 wsB = *reinterpret_cast<const ulonglong2*>(&sws[j0 + 2]);
            const unsigned long long wsp[4] = {wsA.x, wsA.y, wsB.x, wsB.y};

            ulonglong2 vA[5], vB[5];
            #pragma unroll
            for (int k2 = 0; k2 < 5; k2++) {
                vA[k2] = *reinterpret_cast<const ulonglong2*>(&sV[k2][j0]);
                vB[k2] = *reinterpret_cast<const ulonglong2*>(&sV[k2][j0 + 2]);
            }

            #pragma unroll
            for (int jj = 0; jj < 4; jj++) {
                const float x = xs[jj];
                unsigned long long xp, xsq;
                PACK2(xp,  x, x);
                PACK2(xsq, x, x * x);
                FMA2(acc_ls, xsq, wsp[jj]);          // lin += x*w ; x2s += x^2*s
                #pragma unroll
                for (int k2 = 0; k2 < 5; k2++) {
                    const unsigned long long vj =
                        (jj == 0) ? vA[k2].x : (jj == 1) ? vA[k2].y
                                 : (jj == 2) ? vB[k2].x : vB[k2].y;
                    FMA2(acc2[k2], xp, vj);
                }
            }
        }
    }

    #pragma unroll
    for (int m = 1; m <= 2; m <<= 1) {
        unsigned long long t;
        t = __shfl_xor_sync(0xFFFFFFFFu, acc_ls, m); ADD2(acc_ls, acc_ls, t);
        #pragma unroll
        for (int k2 = 0; k2 < 5; k2++) {
            t = __shfl_xor_sync(0xFFFFFFFFu, acc2[k2], m); ADD2(acc2[k2], acc2[k2], t);
        }
    }

    if (sub == 0) {
        float xv0, xv1, lin, x2s;
        UNPACK2(lin, x2s, acc_ls);
        float inter = -x2s;
        #pragma unroll
        for (int k2 = 0; k2 < 5; k2++) {
            UNPACK2(xv0, xv1, acc2[k2]);
            inter = fmaf(xv0, xv0, inter);
            inter = fmaf(xv1, xv1, inter);
        }
        out[row] = 0.5f * inter + lin + fc_b[0] + bu + bi + 4.0f;
    }
}

extern "C" void kernel_launch(void* const* d_in, const int* in_sizes, int n_in,
                              void* d_out, int out_size)
{
    // metadata order: user, item, u_out, i_out, user_emb, item_emb,
    //                 fc_w, fc_b, fm_V, b_users, b_items
    const int*   user     = (const int*)d_in[0];
    const int*   item     = (const int*)d_in[1];
    const float* user_emb = (const float*)d_in[4];
    const float* item_emb = (const float*)d_in[5];
    const float* fc_w     = (const float*)d_in[6];
    const float* fc_b     = (const float*)d_in[7];
    const float* fm_V     = (const float*)d_in[8];
    const float* b_users  = (const float*)d_in[9];
    const float* b_items  = (const float*)d_in[10];
    float* out = (float*)d_out;

    const int nrows = in_sizes[0];

    const int pgrid = (nrows + 255) / 256;
    fm_prefetch_kernel<<<pgrid, 256>>>(user, item, user_emb, item_emb,
                                       b_users, b_items, nrows);

    const int grid = (nrows + 63) / 64;   // 64 rows per 256-thread block
    fm_kernel<<<grid, 256>>>(user, item, user_emb, item_emb,
                             fc_w, fc_b, fm_V, b_users, b_items, out, nrows);
}

// round 16
// speedup vs baseline: 1.3862x; 1.3862x over previous
#include <cuda_runtime.h>

// decoder_fm — R14: bulk-copy gather pipeline.
// The LDG path pins at ~11us regardless of occupancy/mapping (L1tex MSHR
// concurrency cap x DRAM latency). R9 showed the bulk/TMA path moves the same
// random 256B row set ~3x faster. So: gather embedding rows into SMEM with
// cp.async.bulk.shared::cluster.global + mbarrier completion (guaranteed, not
// a droppable prefetch), then run the known-good R7 math from SMEM.

#define PACK2(d, lo, hi)   asm("mov.b64 %0, {%1, %2};" : "=l"(d) : "f"(lo), "f"(hi))
#define UNPACK2(lo, hi, s) asm("mov.b64 {%0, %1}, %2;" : "=f"(lo), "=f"(hi) : "l"(s))
#define FMA2(d, a, b)      asm("fma.rn.f32x2 %0, %1, %2, %3;" : "=l"(d) : "l"(a), "l"(b), "l"(d))
#define ADD2(d, a, b)      asm("add.rn.f32x2 %0, %1, %2;" : "=l"(d) : "l"(a), "l"(b))

__device__ __forceinline__ unsigned smem_u32(const void* p) {
    unsigned a;
    asm("{ .reg .u64 t; cvta.to.shared.u64 t, %1; cvt.u32.u64 %0, t; }" : "=r"(a) : "l"(p));
    return a;
}

#define ROW_STRIDE 132   // 128 floats + 4 pad -> <=2-way LDS conflicts

__global__ __launch_bounds__(256) void fm_kernel(
    const int* __restrict__ user, const int* __restrict__ item,
    const float* __restrict__ user_emb, const float* __restrict__ item_emb,
    const float* __restrict__ fc_w, const float* __restrict__ fc_b,
    const float* __restrict__ fm_V,
    const float* __restrict__ b_users, const float* __restrict__ b_items,
    float* __restrict__ out, int nrows)
{
    __shared__ float2 sws[128];                      // (fc_w[j], s_j)
    __shared__ float2 sV[5][128];                    // V pairs
    __shared__ int    sidx[128];                     // 64 user idx, 64 item idx
    __shared__ __align__(16) float sx[64 * ROW_STRIDE];
    __shared__ __align__(8)  unsigned long long mbar;

    const int tid = threadIdx.x;
    const int blockBase = blockIdx.x * 64;
    const int rowsHere  = min(64, nrows - blockBase);

    // ---- stage indices (coalesced) + init mbarrier ----
    if (tid < 64) {
        sidx[tid] = (tid < rowsHere) ? user[blockBase + tid] : 0;
    } else if (tid < 128) {
        const int r = tid - 64;
        sidx[tid] = (r < rowsHere) ? item[blockBase + r] : 0;
    }
    if (tid == 0) {
        asm volatile("mbarrier.init.shared.b64 [%0], 1;"
                     :: "r"(smem_u32(&mbar)) : "memory");
    }

    // ---- param staging (overlaps with index latency) ----
    if (tid < 128) {
        float v[10];
        #pragma unroll
        for (int k = 0; k < 10; k++) v[k] = fm_V[tid * 10 + k];
        float s = 0.f;
        #pragma unroll
        for (int k = 0; k < 10; k++) s = fmaf(v[k], v[k], s);
        sws[tid] = make_float2(fc_w[tid], s);
        #pragma unroll
        for (int k2 = 0; k2 < 5; k2++)
            sV[k2][tid] = make_float2(v[2 * k2], v[2 * k2 + 1]);
    }
    __syncthreads();   // sidx + mbar.init visible

    const unsigned mb = smem_u32(&mbar);

    // ---- issue 256B bulk copies: thread t -> row t/2, half t&1 ----
    if (tid < 2 * rowsHere) {
        const int r    = tid >> 1;
        const int half = tid & 1;
        const int idx  = half ? sidx[64 + r] : sidx[r];
        const float* src = (half ? item_emb : user_emb) + (long long)idx * 64;
        const unsigned dst = smem_u32(&sx[r * ROW_STRIDE + half * 64]);
        asm volatile(
            "cp.async.bulk.shared::cluster.global.mbarrier::complete_tx::bytes "
            "[%0], [%1], %2, [%3];"
            :: "r"(dst), "l"(src), "r"(256u), "r"(mb) : "memory");
    }
    if (tid == 0) {
        asm volatile("mbarrier.arrive.expect_tx.shared.b64 _, [%0], %1;"
                     :: "r"(mb), "r"((unsigned)(rowsHere * 512)) : "memory");
    }

    // ---- per-row scalars: issue BEFORE the wait so latency hides under it ----
    const int lane = tid & 31;
    const int sub  = lane & 3;
    const int rw   = lane >> 2;
    const int warp = tid >> 5;
    const int rowL = warp * 8 + rw;            // 0..63
    const int row  = blockBase + rowL;
    const bool active = rowL < rowsHere;

    float bu = 0.f, bi = 0.f, fb = 0.f;
    if (active && sub == 0) {
        bu = __ldg(b_users + sidx[rowL]);
        bi = __ldg(b_items + sidx[64 + rowL]);
        fb = __ldg(fc_b);
    }

    // ---- wait for all gathers (acquire) ----
    {
        unsigned done;
        asm volatile(
            "{\n\t.reg .pred p;\n\t"
            "mbarrier.try_wait.parity.acquire.cta.shared::cta.b64 p, [%1], 0;\n\t"
            "selp.b32 %0, 1, 0, p;\n\t}"
            : "=r"(done) : "r"(mb) : "memory");
        if (!done) {
            asm volatile(
                "{\n\t.reg .pred P1;\n\t"
                "WL_%=:\n\t"
                "mbarrier.try_wait.parity.acquire.cta.shared::cta.b64 P1, [%0], 0, 0x989680;\n\t"
                "@P1 bra.uni WD_%=;\n\t"
                "bra.uni WL_%=;\n\t"
                "WD_%=:\n\t}"
                :: "r"(mb) : "memory");
        }
    }

    if (!active) return;

    // ---- R7 math, x now from SMEM ----
    unsigned long long acc_ls = 0ull;
    unsigned long long acc2[5];
    #pragma unroll
    for (int k2 = 0; k2 < 5; k2++) acc2[k2] = 0ull;

    const float* xrow = &sx[rowL * ROW_STRIDE];

    #pragma unroll
    for (int h = 0; h < 2; h++) {
        #pragma unroll
        for (int c = 0; c < 4; c++) {
            const int jl = (c * 4 + sub) * 4;          // 0..60 within half
            const int j0 = h * 64 + jl;                // param index
            const float4 xq = *reinterpret_cast<const float4*>(xrow + h * 64 + jl);
            const float xs[4] = {xq.x, xq.y, xq.z, xq.w};

            const ulonglong2 wsA = *reinterpret_cast<const ulonglong2*>(&sws[j0]);
            const ulonglong2 wsB = *reinterpret_cast<const ulonglong2*>(&sws[j0 + 2]);
            const unsigned long long wsp[4] = {wsA.x, wsA.y, wsB.x, wsB.y};

            ulonglong2 vA[5], vB[5];
            #pragma unroll
            for (int k2 = 0; k2 < 5; k2++) {
                vA[k2] = *reinterpret_cast<const ulonglong2*>(&sV[k2][j0]);
                vB[k2] = *reinterpret_cast<const ulonglong2*>(&sV[k2][j0 + 2]);
            }

            #pragma unroll
            for (int jj = 0; jj < 4; jj++) {
                const float x = xs[jj];
                unsigned long long xp, xsq;
                PACK2(xp,  x, x);
                PACK2(xsq, x, x * x);
                FMA2(acc_ls, xsq, wsp[jj]);            // lin += x*w ; x2s += x^2*s
                #pragma unroll
                for (int k2 = 0; k2 < 5; k2++) {
                    const unsigned long long vj =
                        (jj == 0) ? vA[k2].x : (jj == 1) ? vA[k2].y
                                 : (jj == 2) ? vB[k2].x : vB[k2].y;
                    FMA2(acc2[k2], xp, vj);
                }
            }
        }
    }

    #pragma unroll
    for (int m = 1; m <= 2; m <<= 1) {
        unsigned long long t;
        t = __shfl_xor_sync(0xFFFFFFFFu, acc_ls, m); ADD2(acc_ls, acc_ls, t);
        #pragma unroll
        for (int k2 = 0; k2 < 5; k2++) {
            t = __shfl_xor_sync(0xFFFFFFFFu, acc2[k2], m); ADD2(acc2[k2], acc2[k2], t);
        }
    }

    if (sub == 0) {
        float xv0, xv1, lin, x2s;
        UNPACK2(lin, x2s, acc_ls);
        float inter = -x2s;
        #pragma unroll
        for (int k2 = 0; k2 < 5; k2++) {
            UNPACK2(xv0, xv1, acc2[k2]);
            inter = fmaf(xv0, xv0, inter);
            inter = fmaf(xv1, xv1, inter);
        }
        out[row] = 0.5f * inter + lin + fb + bu + bi + 4.0f;
    }
}

extern "C" void kernel_launch(void* const* d_in, const int* in_sizes, int n_in,
                              void* d_out, int out_size)
{
    // metadata order: user, item, u_out, i_out, user_emb, item_emb,
    //                 fc_w, fc_b, fm_V, b_users, b_items
    const int*   user     = (const int*)d_in[0];
    const int*   item     = (const int*)d_in[1];
    const float* user_emb = (const float*)d_in[4];
    const float* item_emb = (const float*)d_in[5];
    const float* fc_w     = (const float*)d_in[6];
    const float* fc_b     = (const float*)d_in[7];
    const float* fm_V     = (const float*)d_in[8];
    const float* b_users  = (const float*)d_in[9];
    const float* b_items  = (const float*)d_in[10];
    float* out = (float*)d_out;

    const int nrows = in_sizes[0];
    const int grid  = (nrows + 63) / 64;   // 64 rows per 256-thread block
    fm_kernel<<<grid, 256>>>(user, item, user_emb, item_emb,
                             fc_w, fc_b, fm_V, b_users, b_items, out, nrows);
}